// round 13
// baseline (speedup 1.0000x reference)
#include <cuda_runtime.h>
#include <cuda_bf16.h>
#include <math.h>
#include <stdint.h>

#define Bq 8192
#define Fq 26
#define Dq 32
#define Vq 100000
#define Hq 128
#define NPAIR 351
#define KPAD 352       // padded pair count (x1 mma K)
#define KPP_X1 176     // KPAD/2
#define Uq 400
#define KP_CIN2 1664   // 3328/2
#define KP_SPLIT4 416  // quarter of KP_CIN2
#define KP_MLP1 416    // 832/2
#define KP_MLP2 200    // 400/2

typedef unsigned u32;

// ---------------- scratch (no cudaMalloc allowed) ----------------
__device__ float g_wsym[NPAIR * Hq];
__device__ int   g_pij[KPAD];
__device__ __align__(16) u32 g_wBh[Hq * KPP_X1], g_wBl[Hq * KPP_X1];         // n-major [h][kp]
__device__ __align__(16) float g_embed[Bq * Fq * Dq];
__device__ __align__(16) u32 g_Ehi[Bq * KP_MLP1], g_Elo[Bq * KP_MLP1];       // A [m][kp]
__device__ __align__(16) u32 g_Shi[(size_t)Bq * KP_CIN2], g_Slo[(size_t)Bq * KP_CIN2];
__device__ __align__(16) u32 g_Wc1hi[Hq * KP_CIN2], g_Wc1lo[Hq * KP_CIN2];   // n-major [n][kp]
__device__ __align__(16) u32 g_W1hi[512 * KP_MLP1], g_W1lo[512 * KP_MLP1];   // n-major padded
__device__ __align__(16) u32 g_W2hi[512 * KP_MLP2], g_W2lo[512 * KP_MLP2];
__device__ __align__(16) u32 g_H1hi[Bq * KP_MLP2], g_H1lo[Bq * KP_MLP2];     // A [m][kp]
__device__ float g_lin[Bq];
__device__ float g_cin1[Bq * Hq];
__device__ float g_cin2s[4 * Bq * Hq];       // split-K x4 partial sums
__device__ float g_h2[Bq * Uq];

// ---------------- helpers ----------------
__device__ __forceinline__ void split2(float x, float y, u32 &hi, u32 &lo) {
    u32 xh = (u32)__bfloat16_as_ushort(__float2bfloat16_rn(x));
    u32 yh = (u32)__bfloat16_as_ushort(__float2bfloat16_rn(y));
    float xr = x - __uint_as_float(xh << 16);
    float yr = y - __uint_as_float(yh << 16);
    u32 xl = (u32)__bfloat16_as_ushort(__float2bfloat16_rn(xr));
    u32 yl = (u32)__bfloat16_as_ushort(__float2bfloat16_rn(yr));
    hi = xh | (yh << 16);
    lo = xl | (yl << 16);
}
__device__ __forceinline__ void mma16816(float c[4], const u32 a[4], u32 b0, u32 b1) {
    asm volatile(
        "mma.sync.aligned.m16n8k16.row.col.f32.bf16.bf16.f32 "
        "{%0,%1,%2,%3}, {%4,%5,%6,%7}, {%8,%9}, {%0,%1,%2,%3};"
        : "+f"(c[0]), "+f"(c[1]), "+f"(c[2]), "+f"(c[3])
        : "r"(a[0]), "r"(a[1]), "r"(a[2]), "r"(a[3]), "r"(b0), "r"(b1));
}
__device__ __forceinline__ void ldsm4(u32 &r0, u32 &r1, u32 &r2, u32 &r3, u32 addr) {
    asm volatile("ldmatrix.sync.aligned.m8n8.x4.shared.b16 {%0,%1,%2,%3}, [%4];"
                 : "=r"(r0), "=r"(r1), "=r"(r2), "=r"(r3) : "r"(addr));
}
__device__ __forceinline__ void ldsm4t(u32 &r0, u32 &r1, u32 &r2, u32 &r3, u32 addr) {
    asm volatile("ldmatrix.sync.aligned.m8n8.x4.trans.shared.b16 {%0,%1,%2,%3}, [%4];"
                 : "=r"(r0), "=r"(r1), "=r"(r2), "=r"(r3) : "r"(addr));
}
__device__ __forceinline__ u32 smem_u32(const void* p) {
    u32 a;
    asm("{ .reg .u64 t; cvta.to.shared.u64 t, %1; cvt.u32.u64 %0, t; }"
        : "=r"(a) : "l"(p));
    return a;
}

// ---------------- prep1: symmetrize W_cin0 ----------------
__global__ void prep_kernel(const float* __restrict__ W0) {
    int t = blockIdx.x * blockDim.x + threadIdx.x;
    if (t == 0) g_pij[NPAIR] = 0;
    if (t >= NPAIR * Hq) return;
    int p = t >> 7, h = t & 127;
    int i = 0, rem = p;
    while (rem >= Fq - i) { rem -= Fq - i; i++; }
    int j = i + rem;
    float w = W0[(i * Fq + j) * Hq + h];
    if (i != j) w += W0[(j * Fq + i) * Hq + h];
    g_wsym[t] = w;
    if (h == 0) g_pij[p] = i | (j << 8);
}

// ---------------- prep2: wsym -> n-major packed planes [h][kp] ----------------
__global__ void pack_wsymT() {
    int t = blockIdx.x * blockDim.x + threadIdx.x;
    if (t >= Hq * KPP_X1) return;
    int h = t / KPP_X1, kp = t % KPP_X1;
    float w0 = (2 * kp < NPAIR) ? g_wsym[(2 * kp) * Hq + h] : 0.f;
    float w1 = (2 * kp + 1 < NPAIR) ? g_wsym[(2 * kp + 1) * Hq + h] : 0.f;
    split2(w0, w1, g_wBh[t], g_wBl[t]);
}

// ---------------- packB_T: fp32 W[K][N] -> n-major packed [Npad][Kpp] ----------------
__global__ void packB_T(const float* __restrict__ W, int Kreal, int Nreal,
                        int Kpp, int Npad, u32* __restrict__ Oh, u32* __restrict__ Ol) {
    int t = blockIdx.x * blockDim.x + threadIdx.x;
    if (t >= Npad * Kpp) return;
    int n = t / Kpp, kp = t % Kpp;
    float f0 = (n < Nreal && 2 * kp < Kreal) ? W[(size_t)(2 * kp) * Nreal + n] : 0.f;
    float f1 = (n < Nreal && 2 * kp + 1 < Kreal) ? W[(size_t)(2 * kp + 1) * Nreal + n] : 0.f;
    split2(f0, f1, Oh[t], Ol[t]);
}

// ---------------- gather: fp32 embed + packed split for MLP1 ----------------
__global__ void gather_kernel(const int* __restrict__ idx, const float* __restrict__ E) {
    int e = blockIdx.x * blockDim.x + threadIdx.x;
    if (e >= Bq * Fq * (Dq / 4)) return;
    int q = e & 7;
    int r = e >> 3;
    int i = r % Fq;
    int b = r / Fq;
    int v = __ldg(&idx[b * Fq + i]);
    float4 val = __ldg((const float4*)(E + ((size_t)i * Vq + v) * Dq) + q);
    ((float4*)g_embed)[e] = val;
    int u = b * KP_MLP1 + (i * 8 + q) * 2;
    split2(val.x, val.y, g_Ehi[u],     g_Elo[u]);
    split2(val.z, val.w, g_Ehi[u + 1], g_Elo[u + 1]);
}

// ---------------- linear term ----------------
__global__ void lin_kernel(const int* __restrict__ idx, const float* __restrict__ w_lin,
                           const float* __restrict__ b_lin) {
    int b = blockIdx.x * blockDim.x + threadIdx.x;
    if (b >= Bq) return;
    float a = b_lin[0];
#pragma unroll
    for (int f = 0; f < Fq; f++) a += (float)idx[b * Fq + f] * w_lin[f];
    g_lin[b] = a;
}

// ---------------- fused x1 GEMM (4 warps, 64x64 tiles) + tensor-core S/cin1 epilogue ----------------
// block = 4 batch rows, 128 threads; M = 128 (m = bl*32+d), N = 128, K = 352 (22 tiles).
// dyn smem layout identical to round-10/12.
#define X1_SMEM 104832
__global__ __launch_bounds__(128, 2) void x1s_mma_kernel() {
    extern __shared__ char dsm_c[];
    u32*   Ahi  = (u32*)(dsm_c + 0);          // [128 m][12]
    u32*   Alo  = (u32*)(dsm_c + 6144);
    u32*   Bh_s = (u32*)(dsm_c + 12288);      // [128 n][12]
    u32*   Bl_s = (u32*)(dsm_c + 18432);
    u32*   XH   = (u32*)(dsm_c + 0);          // overlay: x1 hi plane, u32 [m][68]
    u32*   XL   = (u32*)(dsm_c + 34816);
    u32*   EH   = (u32*)(dsm_c + 69632);      // E' hi [4*32][20]
    u32*   EL   = (u32*)(dsm_c + 79872);
    float* sx   = (float*)(dsm_c + 90112);
    int*   spij = (int*)(dsm_c + 103424);

    int tid  = threadIdx.x;
    int warp = tid >> 5, lane = tid & 31;
    int gid  = lane >> 2, tg = lane & 3;
    int wm   = warp & 1, wn = warp >> 1;     // 64-row, 64-col warp tiles

    const float* eb = g_embed + (size_t)blockIdx.x * 4 * Fq * Dq;
    for (int e = tid; e < 4 * Fq * Dq; e += 128) sx[e] = eb[e];
    for (int e = tid; e < KPAD; e += 128) spij[e] = g_pij[e];

    float c[4][8][4];
#pragma unroll
    for (int mt = 0; mt < 4; mt++)
#pragma unroll
        for (int nt = 0; nt < 8; nt++)
#pragma unroll
            for (int r = 0; r < 4; r++) c[mt][nt][r] = 0.f;

    int la_off = ((lane & 7) + (lane & 8)) * 12 + ((lane & 16) >> 2);
    int lb_off = ((lane & 7) + ((lane & 16) >> 1)) * 12 + ((lane & 8) >> 1);
    u32 smA = smem_u32(dsm_c);
    u32 smB = smA + 12288;

    __syncthreads();

#pragma unroll 1
    for (int t = 0; t < 22; t++) {
#pragma unroll
        for (int it = 0; it < 8; it++) {      // build A tile 128 m x 8 kp (128 thr)
            int idx = it * 128 + tid;
            int kp = idx >> 7, m = idx & 127;
            int bl = m >> 5, d = m & 31;
            int k0 = t * 16 + kp * 2;
            int pij0 = spij[k0], pij1 = spij[k0 + 1];
            const float* sb = sx + bl * (Fq * Dq) + d;
            float a0 = sb[(pij0 & 255) * Dq] * sb[(pij0 >> 8) * Dq];
            float a1 = sb[(pij1 & 255) * Dq] * sb[(pij1 >> 8) * Dq];
            split2(a0, a1, Ahi[m * 12 + kp], Alo[m * 12 + kp]);
        }
        {   // stage B tile (n-major): thread = row, 2 uint4 per plane
            const uint4* gh = (const uint4*)&g_wBh[tid * KPP_X1 + t * 8];
            const uint4* gl = (const uint4*)&g_wBl[tid * KPP_X1 + t * 8];
            uint4 vh0 = gh[0], vh1 = gh[1];
            uint4 vl0 = gl[0], vl1 = gl[1];
            *(uint4*)&Bh_s[tid * 12]     = vh0;
            *(uint4*)&Bh_s[tid * 12 + 4] = vh1;
            *(uint4*)&Bl_s[tid * 12]     = vl0;
            *(uint4*)&Bl_s[tid * 12 + 4] = vl1;
        }
        __syncthreads();

        u32 ah[4][4], al[4][4];
#pragma unroll
        for (int mt = 0; mt < 4; mt++) {
            u32 ad = smA + ((wm * 64 + mt * 16) * 12 + la_off) * 4;
            ldsm4(ah[mt][0], ah[mt][1], ah[mt][2], ah[mt][3], ad);
            ldsm4(al[mt][0], al[mt][1], al[mt][2], al[mt][3], ad + 6144);
        }
#pragma unroll
        for (int np = 0; np < 4; np++) {
            u32 bd = smB + ((wn * 64 + np * 16) * 12 + lb_off) * 4;
            u32 bh[4], bl[4];
            ldsm4(bh[0], bh[1], bh[2], bh[3], bd);
            ldsm4(bl[0], bl[1], bl[2], bl[3], bd + 6144);
#pragma unroll
            for (int mt = 0; mt < 4; mt++) {
                mma16816(c[mt][2 * np],     ah[mt], bh[0], bh[1]);
                mma16816(c[mt][2 * np],     ah[mt], bl[0], bl[1]);
                mma16816(c[mt][2 * np],     al[mt], bh[0], bh[1]);
                mma16816(c[mt][2 * np + 1], ah[mt], bh[2], bh[3]);
                mma16816(c[mt][2 * np + 1], ah[mt], bl[2], bl[3]);
                mma16816(c[mt][2 * np + 1], al[mt], bh[2], bh[3]);
            }
        }
        __syncthreads();
    }

    // ---- build E' bf16 planes (reads sx; 27th row = ones for cin1) ----
#pragma unroll
    for (int it = 0; it < 16; it++) {
        int e = it * 128 + tid;               // 4*32*16 = 2048 entries
        int kp = e & 15;
        int i  = (e >> 4) & 31;
        int b4 = e >> 9;
        float f0 = 0.f, f1 = 0.f;
        if (i < Fq) {
            f0 = sx[b4 * (Fq * Dq) + i * Dq + 2 * kp];
            f1 = sx[b4 * (Fq * Dq) + i * Dq + 2 * kp + 1];
        } else if (i == Fq) {
            f0 = 1.f; f1 = 1.f;
        }
        u32 hi, lo;
        split2(f0, f1, hi, lo);
        EH[(b4 * 32 + i) * 20 + kp] = hi;
        EL[(b4 * 32 + i) * 20 + kp] = lo;
    }

    // ---- spill x1 as bf16 hi/lo planes [m][h] (u32-packed h-pairs, pitch 68 u32) ----
#pragma unroll
    for (int mt = 0; mt < 4; mt++) {
        int r0 = wm * 64 + mt * 16 + gid;
#pragma unroll
        for (int nt = 0; nt < 8; nt++) {
            int hp = (wn * 64 + nt * 8 + 2 * tg) >> 1;
            u32 hi, lo;
            split2(c[mt][nt][0], c[mt][nt][1], hi, lo);
            XH[r0 * 68 + hp] = hi;
            XL[r0 * 68 + hp] = lo;
            split2(c[mt][nt][2], c[mt][nt][3], hi, lo);
            XH[(r0 + 8) * 68 + hp] = hi;
            XL[(r0 + 8) * 68 + hp] = lo;
        }
    }
    __syncthreads();

    // ---- S-mma: S[b4] = E'[32x32] x x1[32x128]; warp = b4 (full 128 cols) ----
    int bRow0 = blockIdx.x * 4;
    int b4w = warp;
    int b = bRow0 + b4w;

    float c2[2][16][4];
#pragma unroll
    for (int mt = 0; mt < 2; mt++)
#pragma unroll
        for (int nt = 0; nt < 16; nt++)
#pragma unroll
            for (int r = 0; r < 4; r++) c2[mt][nt][r] = 0.f;

    u32 smEH = smem_u32(dsm_c) + 69632;
    u32 smXH = smem_u32(dsm_c);
    int la2 = ((lane & 7) + (lane & 8)) * 20 + ((lane & 16) >> 2);
    int lb2_bytes = (lane & 15) * 272 + ((lane & 16) >> 4) * 16;

#pragma unroll
    for (int kt = 0; kt < 2; kt++) {
        u32 aH[2][4], aL[2][4];
#pragma unroll
        for (int mt = 0; mt < 2; mt++) {
            u32 ad = smEH + ((b4w * 32 + mt * 16) * 20 + kt * 8 + la2) * 4;
            ldsm4(aH[mt][0], aH[mt][1], aH[mt][2], aH[mt][3], ad);
            ldsm4(aL[mt][0], aL[mt][1], aL[mt][2], aL[mt][3], ad + 10240);
        }
#pragma unroll
        for (int ng = 0; ng < 8; ng++) {
            u32 badr = smXH + (b4w * 32 + kt * 16) * 272
                     + (ng * 16) * 2 + lb2_bytes;
            u32 bh[4], bl[4];
            ldsm4t(bh[0], bh[1], bh[2], bh[3], badr);
            ldsm4t(bl[0], bl[1], bl[2], bl[3], badr + 34816);
#pragma unroll
            for (int mt = 0; mt < 2; mt++) {
                mma16816(c2[mt][2 * ng],     aH[mt], bh[0], bh[1]);
                mma16816(c2[mt][2 * ng],     aH[mt], bl[0], bl[1]);
                mma16816(c2[mt][2 * ng],     aL[mt], bh[0], bh[1]);
                mma16816(c2[mt][2 * ng + 1], aH[mt], bh[2], bh[3]);
                mma16816(c2[mt][2 * ng + 1], aH[mt], bl[2], bl[3]);
                mma16816(c2[mt][2 * ng + 1], aL[mt], bh[2], bh[3]);
            }
        }
    }

    // ---- write S (packed) + cin1 (ones row, i == 26) ----
#pragma unroll
    for (int mt = 0; mt < 2; mt++) {
#pragma unroll
        for (int nt = 0; nt < 16; nt++) {
            int h  = nt * 8 + 2 * tg;
            int hp = h >> 1;
            int i1 = mt * 16 + gid;          // always < 26
            int i2 = i1 + 8;
            u32 hi, lo;
            split2(c2[mt][nt][0], c2[mt][nt][1], hi, lo);
            g_Shi[(size_t)b * KP_CIN2 + i1 * 64 + hp] = hi;
            g_Slo[(size_t)b * KP_CIN2 + i1 * 64 + hp] = lo;
            if (i2 < Fq) {
                split2(c2[mt][nt][2], c2[mt][nt][3], hi, lo);
                g_Shi[(size_t)b * KP_CIN2 + i2 * 64 + hp] = hi;
                g_Slo[(size_t)b * KP_CIN2 + i2 * 64 + hp] = lo;
            } else if (i2 == Fq) {
                g_cin1[b * Hq + h]     = c2[mt][nt][2];
                g_cin1[b * Hq + h + 1] = c2[mt][nt][3];
            }
        }
    }
}

// ---------------- packed GEMM (ldmatrix + split-K via blockIdx.z) ----------------
// BM=128, BN=128, BK=16 (8 kp); A [M][pitchA] row-major, B n-major [Npad][pitchB].
#define G_SMEM 49152
__global__ __launch_bounds__(256) void gemm_pk(
    const u32* __restrict__ Agh, const u32* __restrict__ Agl, int pitchA,
    const u32* __restrict__ Bgh, const u32* __restrict__ Bgl, int pitchB, int N,
    int kpSeg, int Mtot,
    const float* __restrict__ bias, int relu,
    float* __restrict__ Cf, u32* __restrict__ Ch, u32* __restrict__ Cl)
{
    extern __shared__ char dsm_c[];
    u32* dsm = (u32*)dsm_c;
    int tid  = threadIdx.x;
    int warp = tid >> 5, lane = tid & 31;
    int gid  = lane >> 2, tg = lane & 3;
    int wm   = warp & 3, wn = warp >> 2;
    int m0 = blockIdx.y * 128, n0 = blockIdx.x * 128;
    int kpOff = blockIdx.z * kpSeg;
    if (Cf) Cf += (size_t)blockIdx.z * Mtot * N;

    int sr = tid >> 1, sq = tid & 1;
    const u32* pAh = Agh + (size_t)(m0 + sr) * pitchA + kpOff + sq * 4;
    const u32* pAl = Agl + (size_t)(m0 + sr) * pitchA + kpOff + sq * 4;
    const u32* pBh = Bgh + (size_t)(n0 + sr) * pitchB + kpOff + sq * 4;
    const u32* pBl = Bgl + (size_t)(n0 + sr) * pitchB + kpOff + sq * 4;
    int sidx = sr * 12 + sq * 4;

    int la_off = ((lane & 7) + (lane & 8)) * 12 + ((lane & 16) >> 2);
    int lb_off = ((lane & 7) + ((lane & 16) >> 1)) * 12 + ((lane & 8) >> 1);
    u32 smbase = smem_u32(dsm_c);

    float c[2][8][4];
#pragma unroll
    for (int mt = 0; mt < 2; mt++)
#pragma unroll
        for (int nt = 0; nt < 8; nt++)
#pragma unroll
            for (int r = 0; r < 4; r++) c[mt][nt][r] = 0.f;

    int T = kpSeg >> 3;
    {   // prologue: stage tile 0 into buf 0
        uint4 xah = *(const uint4*)pAh;
        uint4 xal = *(const uint4*)pAl;
        uint4 xbh = *(const uint4*)pBh;
        uint4 xbl = *(const uint4*)pBl;
        *(uint4*)&dsm[sidx]        = xah;
        *(uint4*)&dsm[3072 + sidx] = xal;
        *(uint4*)&dsm[6144 + sidx] = xbh;
        *(uint4*)&dsm[9216 + sidx] = xbl;
    }
    __syncthreads();
    int buf = 0;

#pragma unroll 1
    for (int t = 0; t < T; t++) {
        uint4 xah, xal, xbh, xbl;
        bool have = (t + 1 < T);
        if (have) {
            int o = (t + 1) * 8;
            xah = *(const uint4*)(pAh + o);
            xal = *(const uint4*)(pAl + o);
            xbh = *(const uint4*)(pBh + o);
            xbl = *(const uint4*)(pBl + o);
        }

        u32 aBase = smbase + (buf * 1536) * 4;
        u32 bBase = smbase + ((6144 + buf * 1536)) * 4;
        u32 ah[2][4], al[2][4];
#pragma unroll
        for (int mt = 0; mt < 2; mt++) {
            u32 ad = aBase + ((wm * 32 + mt * 16) * 12 + la_off) * 4;
            ldsm4(ah[mt][0], ah[mt][1], ah[mt][2], ah[mt][3], ad);
            ldsm4(al[mt][0], al[mt][1], al[mt][2], al[mt][3], ad + 3072 * 4);
        }
#pragma unroll
        for (int np = 0; np < 4; np++) {
            u32 bd = bBase + ((wn * 64 + np * 16) * 12 + lb_off) * 4;
            u32 bh[4], bl[4];
            ldsm4(bh[0], bh[1], bh[2], bh[3], bd);
            ldsm4(bl[0], bl[1], bl[2], bl[3], bd + 3072 * 4);
#pragma unroll
            for (int mt = 0; mt < 2; mt++) {
                mma16816(c[mt][2 * np],     ah[mt], bh[0], bh[1]);
                mma16816(c[mt][2 * np],     ah[mt], bl[0], bl[1]);
                mma16816(c[mt][2 * np],     al[mt], bh[0], bh[1]);
                mma16816(c[mt][2 * np + 1], ah[mt], bh[2], bh[3]);
                mma16816(c[mt][2 * np + 1], ah[mt], bl[2], bl[3]);
                mma16816(c[mt][2 * np + 1], al[mt], bh[2], bh[3]);
            }
        }

        if (have) {
            int nb = buf ^ 1;
            *(uint4*)&dsm[nb * 1536 + sidx]        = xah;
            *(uint4*)&dsm[3072 + nb * 1536 + sidx] = xal;
            *(uint4*)&dsm[6144 + nb * 1536 + sidx] = xbh;
            *(uint4*)&dsm[9216 + nb * 1536 + sidx] = xbl;
            __syncthreads();
            buf = nb;
        }
    }

    // epilogue
    int Np = N >> 1;
#pragma unroll
    for (int mt = 0; mt < 2; mt++) {
        int r0 = m0 + wm * 32 + mt * 16 + gid;
#pragma unroll
        for (int nt = 0; nt < 8; nt++) {
            int col = n0 + wn * 64 + nt * 8 + 2 * tg;
            if (col >= N) continue;
            float b0v = bias ? bias[col] : 0.f;
            float b1v = bias ? bias[col + 1] : 0.f;
            float v0 = c[mt][nt][0] + b0v, v1 = c[mt][nt][1] + b1v;
            float v2 = c[mt][nt][2] + b0v, v3 = c[mt][nt][3] + b1v;
            if (relu) {
                v0 = fmaxf(v0, 0.f); v1 = fmaxf(v1, 0.f);
                v2 = fmaxf(v2, 0.f); v3 = fmaxf(v3, 0.f);
            }
            if (Cf) {
                *(float2*)&Cf[(size_t)r0 * N + col]       = make_float2(v0, v1);
                *(float2*)&Cf[(size_t)(r0 + 8) * N + col] = make_float2(v2, v3);
            }
            if (Ch) {
                u32 hi, lo;
                split2(v0, v1, hi, lo);
                Ch[(size_t)r0 * Np + (col >> 1)] = hi;
                Cl[(size_t)r0 * Np + (col >> 1)] = lo;
                split2(v2, v3, hi, lo);
                Ch[(size_t)(r0 + 8) * Np + (col >> 1)] = hi;
                Cl[(size_t)(r0 + 8) * Np + (col >> 1)] = lo;
            }
        }
    }
}

// ---------------- final head ----------------
__global__ void final_kernel(const float* __restrict__ dense,
                             const float* __restrict__ w_out,
                             const float* __restrict__ b_out,
                             float* __restrict__ out) {
    int gt = blockIdx.x * blockDim.x + threadIdx.x;
    int b = gt >> 5, lane = gt & 31;
    if (b >= Bq) return;
    float a = 0.f;
    const float* c1 = g_cin1 + b * Hq;
    const float* c2a = g_cin2s + b * Hq;
    const float* c2b = g_cin2s + 1 * Bq * Hq + b * Hq;
    const float* c2c = g_cin2s + 2 * Bq * Hq + b * Hq;
    const float* c2d = g_cin2s + 3 * Bq * Hq + b * Hq;
    const float* hh = g_h2 + b * Uq;
    for (int t = lane; t < Hq; t += 32) a += c1[t] * w_out[1 + t];
    for (int t = lane; t < Hq; t += 32)
        a += (c2a[t] + c2b[t] + c2c[t] + c2d[t]) * w_out[1 + Hq + t];
    for (int t = lane; t < Uq; t += 32) a += hh[t] * w_out[1 + 2 * Hq + t];
    if (lane < 13) a += dense[b * 13 + lane] * w_out[1 + 2 * Hq + Uq + lane];
#pragma unroll
    for (int o = 16; o > 0; o >>= 1) a += __shfl_down_sync(0xffffffffu, a, o);
    if (lane == 0) {
        float tot = a + g_lin[b] * w_out[0] + b_out[0];
        float o;
        if (tot >= 0.f) { o = 1.f / (1.f + expf(-tot)); }
        else            { float e = expf(tot); o = e / (1.f + e); }
        out[b] = o;
    }
}

extern "C" void kernel_launch(void* const* d_in, const int* in_sizes, int n_in,
                              void* d_out, int out_size) {
    (void)in_sizes; (void)n_in; (void)out_size;
    const float* dense  = (const float*)d_in[0];
    const int*   sparse = (const int*)  d_in[1];
    const float* E      = (const float*)d_in[2];
    const float* W0     = (const float*)d_in[3];
    const float* Wc1    = (const float*)d_in[4];
    const float* W1     = (const float*)d_in[5];
    const float* b1     = (const float*)d_in[6];
    const float* W2     = (const float*)d_in[7];
    const float* b2     = (const float*)d_in[8];
    const float* w_lin  = (const float*)d_in[9];
    const float* b_lin  = (const float*)d_in[10];
    const float* w_out  = (const float*)d_in[11];
    const float* b_out  = (const float*)d_in[12];
    float* out = (float*)d_out;

    static int smem_set = 0;
    if (!smem_set) {
        cudaFuncSetAttribute(x1s_mma_kernel,
                             cudaFuncAttributeMaxDynamicSharedMemorySize, X1_SMEM);
        cudaFuncSetAttribute(gemm_pk,
                             cudaFuncAttributeMaxDynamicSharedMemorySize, G_SMEM);
        smem_set = 1;
    }

    void *pShi, *pSlo, *pEhi, *pElo, *pWc1hi, *pWc1lo, *pW1hi, *pW1lo,
         *pW2hi, *pW2lo, *pH1hi, *pH1lo, *pC2, *pH2;
    cudaGetSymbolAddress(&pShi, g_Shi);   cudaGetSymbolAddress(&pSlo, g_Slo);
    cudaGetSymbolAddress(&pEhi, g_Ehi);   cudaGetSymbolAddress(&pElo, g_Elo);
    cudaGetSymbolAddress(&pWc1hi, g_Wc1hi); cudaGetSymbolAddress(&pWc1lo, g_Wc1lo);
    cudaGetSymbolAddress(&pW1hi, g_W1hi); cudaGetSymbolAddress(&pW1lo, g_W1lo);
    cudaGetSymbolAddress(&pW2hi, g_W2hi); cudaGetSymbolAddress(&pW2lo, g_W2lo);
    cudaGetSymbolAddress(&pH1hi, g_H1hi); cudaGetSymbolAddress(&pH1lo, g_H1lo);
    cudaGetSymbolAddress(&pC2, g_cin2s);  cudaGetSymbolAddress(&pH2, g_h2);

    // launches 1-3 are x1's dependencies; x1 is launch #4 (ncu captures #4)
    prep_kernel<<<(NPAIR * Hq + 255) / 256, 256>>>(W0);
    pack_wsymT<<<(Hq * KPP_X1 + 255) / 256, 256>>>();
    gather_kernel<<<(Bq * Fq * (Dq / 4) + 255) / 256, 256>>>(sparse, E);

    x1s_mma_kernel<<<Bq / 4, 128, X1_SMEM>>>();

    lin_kernel<<<(Bq + 255) / 256, 256>>>(sparse, w_lin, b_lin);
    packB_T<<<(Hq * KP_CIN2 + 255) / 256, 256>>>(
        Wc1, Fq * Hq, Hq, KP_CIN2, Hq, (u32*)pWc1hi, (u32*)pWc1lo);
    packB_T<<<(512 * KP_MLP1 + 255) / 256, 256>>>(
        W1, Fq * Dq, Uq, KP_MLP1, 512, (u32*)pW1hi, (u32*)pW1lo);
    packB_T<<<(512 * KP_MLP2 + 255) / 256, 256>>>(
        W2, Uq, Uq, KP_MLP2, 512, (u32*)pW2hi, (u32*)pW2lo);

    // cin2 = S @ Wc1, split-K x4 in one launch (grid.z = 4, 256 blocks)
    gemm_pk<<<dim3(1, Bq / 128, 4), 256, G_SMEM>>>(
        (const u32*)pShi, (const u32*)pSlo, KP_CIN2,
        (const u32*)pWc1hi, (const u32*)pWc1lo, KP_CIN2, Hq,
        KP_SPLIT4, Bq, nullptr, 0, (float*)pC2, nullptr, nullptr);
    // h1 = relu(embed @ W1 + b1) -> packed split only
    gemm_pk<<<dim3((Uq + 127) / 128, Bq / 128, 1), 256, G_SMEM>>>(
        (const u32*)pEhi, (const u32*)pElo, KP_MLP1,
        (const u32*)pW1hi, (const u32*)pW1lo, KP_MLP1, Uq,
        KP_MLP1, Bq, b1, 1, nullptr, (u32*)pH1hi, (u32*)pH1lo);
    // h2 = relu(h1 @ W2 + b2) -> fp32
    gemm_pk<<<dim3((Uq + 127) / 128, Bq / 128, 1), 256, G_SMEM>>>(
        (const u32*)pH1hi, (const u32*)pH1lo, KP_MLP2,
        (const u32*)pW2hi, (const u32*)pW2lo, KP_MLP2, Uq,
        KP_MLP2, Bq, b2, 1, (float*)pH2, nullptr, nullptr);

    final_kernel<<<(Bq * 32 + 255) / 256, 256>>>(dense, w_out, b_out, out);
}

// round 14
// speedup vs baseline: 1.0912x; 1.0912x over previous
#include <cuda_runtime.h>
#include <cuda_bf16.h>
#include <math.h>
#include <stdint.h>

#define Bq 8192
#define Fq 26
#define Dq 32
#define Vq 100000
#define Hq 128
#define NPAIR 351
#define KPAD 352       // padded pair count (x1 mma K)
#define KPP_X1 176     // KPAD/2
#define Uq 400
#define KP_CIN2 1664   // 3328/2
#define KP_SPLIT4 416  // quarter of KP_CIN2
#define KP_MLP1 416    // 832/2
#define KP_MLP2 200    // 400/2

typedef unsigned u32;

// ---------------- scratch (no cudaMalloc allowed) ----------------
__device__ float g_wsym[NPAIR * Hq];
__device__ int   g_pij[KPAD];
__device__ __align__(16) u32 g_wBh[Hq * KPP_X1], g_wBl[Hq * KPP_X1];         // n-major [h][kp]
__device__ __align__(16) u32 g_Ehi[Bq * KP_MLP1], g_Elo[Bq * KP_MLP1];       // A [m][kp]
__device__ __align__(16) u32 g_Shi[(size_t)Bq * KP_CIN2], g_Slo[(size_t)Bq * KP_CIN2];
__device__ __align__(16) u32 g_Wc1hi[Hq * KP_CIN2], g_Wc1lo[Hq * KP_CIN2];   // n-major [n][kp]
__device__ __align__(16) u32 g_W1hi[512 * KP_MLP1], g_W1lo[512 * KP_MLP1];   // n-major padded
__device__ __align__(16) u32 g_W2hi[512 * KP_MLP2], g_W2lo[512 * KP_MLP2];
__device__ __align__(16) u32 g_H1hi[Bq * KP_MLP2], g_H1lo[Bq * KP_MLP2];     // A [m][kp]
__device__ float g_lin[Bq];
__device__ float g_cin1[Bq * Hq];
__device__ float g_cin2s[4 * Bq * Hq];       // split-K x4 partial sums
__device__ float g_h2[Bq * Uq];

// ---------------- helpers ----------------
__device__ __forceinline__ void split2(float x, float y, u32 &hi, u32 &lo) {
    u32 xh = (u32)__bfloat16_as_ushort(__float2bfloat16_rn(x));
    u32 yh = (u32)__bfloat16_as_ushort(__float2bfloat16_rn(y));
    float xr = x - __uint_as_float(xh << 16);
    float yr = y - __uint_as_float(yh << 16);
    u32 xl = (u32)__bfloat16_as_ushort(__float2bfloat16_rn(xr));
    u32 yl = (u32)__bfloat16_as_ushort(__float2bfloat16_rn(yr));
    hi = xh | (yh << 16);
    lo = xl | (yl << 16);
}
__device__ __forceinline__ void mma16816(float c[4], const u32 a[4], u32 b0, u32 b1) {
    asm volatile(
        "mma.sync.aligned.m16n8k16.row.col.f32.bf16.bf16.f32 "
        "{%0,%1,%2,%3}, {%4,%5,%6,%7}, {%8,%9}, {%0,%1,%2,%3};"
        : "+f"(c[0]), "+f"(c[1]), "+f"(c[2]), "+f"(c[3])
        : "r"(a[0]), "r"(a[1]), "r"(a[2]), "r"(a[3]), "r"(b0), "r"(b1));
}
__device__ __forceinline__ void ldsm4(u32 &r0, u32 &r1, u32 &r2, u32 &r3, u32 addr) {
    asm volatile("ldmatrix.sync.aligned.m8n8.x4.shared.b16 {%0,%1,%2,%3}, [%4];"
                 : "=r"(r0), "=r"(r1), "=r"(r2), "=r"(r3) : "r"(addr));
}
__device__ __forceinline__ void ldsm4t(u32 &r0, u32 &r1, u32 &r2, u32 &r3, u32 addr) {
    asm volatile("ldmatrix.sync.aligned.m8n8.x4.trans.shared.b16 {%0,%1,%2,%3}, [%4];"
                 : "=r"(r0), "=r"(r1), "=r"(r2), "=r"(r3) : "r"(addr));
}
__device__ __forceinline__ u32 smem_u32(const void* p) {
    u32 a;
    asm("{ .reg .u64 t; cvta.to.shared.u64 t, %1; cvt.u32.u64 %0, t; }"
        : "=r"(a) : "l"(p));
    return a;
}

// ---------------- prep1: symmetrize W_cin0 ----------------
__global__ void prep_kernel(const float* __restrict__ W0) {
    int t = blockIdx.x * blockDim.x + threadIdx.x;
    if (t == 0) g_pij[NPAIR] = 0;
    if (t >= NPAIR * Hq) return;
    int p = t >> 7, h = t & 127;
    int i = 0, rem = p;
    while (rem >= Fq - i) { rem -= Fq - i; i++; }
    int j = i + rem;
    float w = W0[(i * Fq + j) * Hq + h];
    if (i != j) w += W0[(j * Fq + i) * Hq + h];
    g_wsym[t] = w;
    if (h == 0) g_pij[p] = i | (j << 8);
}

// ---------------- prep2: wsym -> n-major packed planes [h][kp] ----------------
__global__ void pack_wsymT() {
    int t = blockIdx.x * blockDim.x + threadIdx.x;
    if (t >= Hq * KPP_X1) return;
    int h = t / KPP_X1, kp = t % KPP_X1;
    float w0 = (2 * kp < NPAIR) ? g_wsym[(2 * kp) * Hq + h] : 0.f;
    float w1 = (2 * kp + 1 < NPAIR) ? g_wsym[(2 * kp + 1) * Hq + h] : 0.f;
    split2(w0, w1, g_wBh[t], g_wBl[t]);
}

// ---------------- packB_T: fp32 W[K][N] -> n-major packed [Npad][Kpp] ----------------
__global__ void packB_T(const float* __restrict__ W, int Kreal, int Nreal,
                        int Kpp, int Npad, u32* __restrict__ Oh, u32* __restrict__ Ol) {
    int t = blockIdx.x * blockDim.x + threadIdx.x;
    if (t >= Npad * Kpp) return;
    int n = t / Kpp, kp = t % Kpp;
    float f0 = (n < Nreal && 2 * kp < Kreal) ? W[(size_t)(2 * kp) * Nreal + n] : 0.f;
    float f1 = (n < Nreal && 2 * kp + 1 < Kreal) ? W[(size_t)(2 * kp + 1) * Nreal + n] : 0.f;
    split2(f0, f1, Oh[t], Ol[t]);
}

// ---------------- gather: packed bf16 split planes for MLP1 (no fp32 embed) ----------------
__global__ void gather_kernel(const int* __restrict__ idx, const float* __restrict__ E) {
    int e = blockIdx.x * blockDim.x + threadIdx.x;
    if (e >= Bq * Fq * (Dq / 4)) return;
    int q = e & 7;
    int r = e >> 3;
    int i = r % Fq;
    int b = r / Fq;
    int v = __ldg(&idx[b * Fq + i]);
    float4 val = __ldg((const float4*)(E + ((size_t)i * Vq + v) * Dq) + q);
    int u = b * KP_MLP1 + (i * 8 + q) * 2;
    split2(val.x, val.y, g_Ehi[u],     g_Elo[u]);
    split2(val.z, val.w, g_Ehi[u + 1], g_Elo[u + 1]);
}

// ---------------- linear term ----------------
__global__ void lin_kernel(const int* __restrict__ idx, const float* __restrict__ w_lin,
                           const float* __restrict__ b_lin) {
    int b = blockIdx.x * blockDim.x + threadIdx.x;
    if (b >= Bq) return;
    float a = b_lin[0];
#pragma unroll
    for (int f = 0; f < Fq; f++) a += (float)idx[b * Fq + f] * w_lin[f];
    g_lin[b] = a;
}

// ---------------- fused x1 GEMM + tensor-core S/cin1 epilogue (round-12 structure) ----------------
// block = 4 batch rows; M = 128 (m = bl*32+d), N = 128, K = 352 (22 tiles).
// sx gathered directly from E via sparse indices (rows L2-warm from gather_kernel).
#define X1_SMEM 104832
__global__ __launch_bounds__(256, 2) void x1s_mma_kernel(
    const int* __restrict__ idx, const float* __restrict__ E)
{
    extern __shared__ char dsm_c[];
    u32*   Ahi  = (u32*)(dsm_c + 0);          // [128 m][12]
    u32*   Alo  = (u32*)(dsm_c + 6144);
    u32*   Bh_s = (u32*)(dsm_c + 12288);      // [128 n][12]
    u32*   Bl_s = (u32*)(dsm_c + 18432);
    u32*   XH   = (u32*)(dsm_c + 0);          // overlay: x1 hi plane, u32 [m][68]
    u32*   XL   = (u32*)(dsm_c + 34816);
    u32*   EH   = (u32*)(dsm_c + 69632);      // E' hi [4*32][20]
    u32*   EL   = (u32*)(dsm_c + 79872);
    float* sx   = (float*)(dsm_c + 90112);
    int*   spij = (int*)(dsm_c + 103424);

    int tid  = threadIdx.x;
    int warp = tid >> 5, lane = tid & 31;
    int gid  = lane >> 2, tg = lane & 3;
    int wm   = warp & 3, wn = warp >> 2;

    // gather sx directly from E: 832 float4 (4 rows x 26 fields x 8 quads)
    int bRow0 = blockIdx.x * 4;
    for (int e = tid; e < 4 * Fq * (Dq / 4); e += 256) {
        int q = e & 7;
        int r = e >> 3;
        int i = r % Fq;
        int b4 = r / Fq;
        int v = __ldg(&idx[(bRow0 + b4) * Fq + i]);
        ((float4*)sx)[e] = __ldg((const float4*)(E + ((size_t)i * Vq + v) * Dq) + q);
    }
    for (int e = tid; e < KPAD; e += 256) spij[e] = g_pij[e];

    float c[2][8][4];
#pragma unroll
    for (int mt = 0; mt < 2; mt++)
#pragma unroll
        for (int nt = 0; nt < 8; nt++)
#pragma unroll
            for (int r = 0; r < 4; r++) c[mt][nt][r] = 0.f;

    int la_off = ((lane & 7) + (lane & 8)) * 12 + ((lane & 16) >> 2);
    int lb_off = ((lane & 7) + ((lane & 16) >> 1)) * 12 + ((lane & 8) >> 1);
    u32 smA = smem_u32(dsm_c);
    u32 smB = smA + 12288;

    int bn = tid >> 1, bq = tid & 1;

    __syncthreads();

#pragma unroll 1
    for (int t = 0; t < 22; t++) {
#pragma unroll
        for (int it = 0; it < 4; it++) {      // build A tile 128 m x 8 kp
            int idx2 = it * 256 + tid;
            int kp = idx2 >> 7, m = idx2 & 127;
            int bl = m >> 5, d = m & 31;
            int k0 = t * 16 + kp * 2;
            int pij0 = spij[k0], pij1 = spij[k0 + 1];
            const float* sb = sx + bl * (Fq * Dq) + d;
            float a0 = sb[(pij0 & 255) * Dq] * sb[(pij0 >> 8) * Dq];
            float a1 = sb[(pij1 & 255) * Dq] * sb[(pij1 >> 8) * Dq];
            split2(a0, a1, Ahi[m * 12 + kp], Alo[m * 12 + kp]);
        }
        {   // stage B tile (n-major): 128 n x 8 kp, 1 uint4/thread/plane
            uint4 vh = *(const uint4*)&g_wBh[bn * KPP_X1 + t * 8 + bq * 4];
            uint4 vl = *(const uint4*)&g_wBl[bn * KPP_X1 + t * 8 + bq * 4];
            *(uint4*)&Bh_s[bn * 12 + bq * 4] = vh;
            *(uint4*)&Bl_s[bn * 12 + bq * 4] = vl;
        }
        __syncthreads();

        u32 ah[2][4], al[2][4];
#pragma unroll
        for (int mt = 0; mt < 2; mt++) {
            u32 ad = smA + ((wm * 32 + mt * 16) * 12 + la_off) * 4;
            ldsm4(ah[mt][0], ah[mt][1], ah[mt][2], ah[mt][3], ad);
            ldsm4(al[mt][0], al[mt][1], al[mt][2], al[mt][3], ad + 6144);
        }
#pragma unroll
        for (int np = 0; np < 4; np++) {
            u32 bd = smB + ((wn * 64 + np * 16) * 12 + lb_off) * 4;
            u32 bh[4], bl[4];
            ldsm4(bh[0], bh[1], bh[2], bh[3], bd);
            ldsm4(bl[0], bl[1], bl[2], bl[3], bd + 6144);
#pragma unroll
            for (int mt = 0; mt < 2; mt++) {
                mma16816(c[mt][2 * np],     ah[mt], bh[0], bh[1]);
                mma16816(c[mt][2 * np],     ah[mt], bl[0], bl[1]);
                mma16816(c[mt][2 * np],     al[mt], bh[0], bh[1]);
                mma16816(c[mt][2 * np + 1], ah[mt], bh[2], bh[3]);
                mma16816(c[mt][2 * np + 1], ah[mt], bl[2], bl[3]);
                mma16816(c[mt][2 * np + 1], al[mt], bh[2], bh[3]);
            }
        }
        __syncthreads();
    }

    // ---- build E' bf16 planes (reads sx; 27th row = ones for cin1) ----
#pragma unroll
    for (int it = 0; it < 8; it++) {
        int e = it * 256 + tid;               // 4*32*16 = 2048 entries
        int kp = e & 15;
        int i  = (e >> 4) & 31;
        int b4 = e >> 9;
        float f0 = 0.f, f1 = 0.f;
        if (i < Fq) {
            f0 = sx[b4 * (Fq * Dq) + i * Dq + 2 * kp];
            f1 = sx[b4 * (Fq * Dq) + i * Dq + 2 * kp + 1];
        } else if (i == Fq) {
            f0 = 1.f; f1 = 1.f;
        }
        u32 hi, lo;
        split2(f0, f1, hi, lo);
        EH[(b4 * 32 + i) * 20 + kp] = hi;
        EL[(b4 * 32 + i) * 20 + kp] = lo;
    }

    // ---- spill x1 as bf16 hi/lo planes [m][h] (u32-packed h-pairs, pitch 68 u32) ----
#pragma unroll
    for (int mt = 0; mt < 2; mt++) {
        int r0 = wm * 32 + mt * 16 + gid;
#pragma unroll
        for (int nt = 0; nt < 8; nt++) {
            int hp = (wn * 64 + nt * 8 + 2 * tg) >> 1;
            u32 hi, lo;
            split2(c[mt][nt][0], c[mt][nt][1], hi, lo);
            XH[r0 * 68 + hp] = hi;
            XL[r0 * 68 + hp] = lo;
            split2(c[mt][nt][2], c[mt][nt][3], hi, lo);
            XH[(r0 + 8) * 68 + hp] = hi;
            XL[(r0 + 8) * 68 + hp] = lo;
        }
    }
    __syncthreads();

    // ---- S-mma: S[b4] = E'[32x32] x x1[32x128]; warp = (b4, h-half) ----
    int wn2 = warp & 1, b4w = warp >> 1;
    int b = bRow0 + b4w;

    float c2[2][8][4];
#pragma unroll
    for (int mt = 0; mt < 2; mt++)
#pragma unroll
        for (int nt = 0; nt < 8; nt++)
#pragma unroll
            for (int r = 0; r < 4; r++) c2[mt][nt][r] = 0.f;

    u32 smEH = smem_u32(dsm_c) + 69632;
    u32 smXH = smem_u32(dsm_c);
    int la2 = ((lane & 7) + (lane & 8)) * 20 + ((lane & 16) >> 2);
    int lb2_bytes = (lane & 15) * 272 + ((lane & 16) >> 4) * 16;

#pragma unroll
    for (int kt = 0; kt < 2; kt++) {
        u32 aH[2][4], aL[2][4];
#pragma unroll
        for (int mt = 0; mt < 2; mt++) {
            u32 ad = smEH + ((b4w * 32 + mt * 16) * 20 + kt * 8 + la2) * 4;
            ldsm4(aH[mt][0], aH[mt][1], aH[mt][2], aH[mt][3], ad);
            ldsm4(aL[mt][0], aL[mt][1], aL[mt][2], aL[mt][3], ad + 10240);
        }
#pragma unroll
        for (int ng = 0; ng < 4; ng++) {
            u32 badr = smXH + (b4w * 32 + kt * 16) * 272
                     + (wn2 * 64 + ng * 16) * 2 + lb2_bytes;
            u32 bh[4], bl[4];
            ldsm4t(bh[0], bh[1], bh[2], bh[3], badr);
            ldsm4t(bl[0], bl[1], bl[2], bl[3], badr + 34816);
#pragma unroll
            for (int mt = 0; mt < 2; mt++) {
                mma16816(c2[mt][2 * ng],     aH[mt], bh[0], bh[1]);
                mma16816(c2[mt][2 * ng],     aH[mt], bl[0], bl[1]);
                mma16816(c2[mt][2 * ng],     aL[mt], bh[0], bh[1]);
                mma16816(c2[mt][2 * ng + 1], aH[mt], bh[2], bh[3]);
                mma16816(c2[mt][2 * ng + 1], aH[mt], bl[2], bl[3]);
                mma16816(c2[mt][2 * ng + 1], aL[mt], bh[2], bh[3]);
            }
        }
    }

    // ---- write S (packed) + cin1 (ones row, i == 26) ----
#pragma unroll
    for (int mt = 0; mt < 2; mt++) {
#pragma unroll
        for (int nt = 0; nt < 8; nt++) {
            int h  = wn2 * 64 + nt * 8 + 2 * tg;
            int hp = h >> 1;
            int i1 = mt * 16 + gid;          // always < 26
            int i2 = i1 + 8;
            u32 hi, lo;
            split2(c2[mt][nt][0], c2[mt][nt][1], hi, lo);
            g_Shi[(size_t)b * KP_CIN2 + i1 * 64 + hp] = hi;
            g_Slo[(size_t)b * KP_CIN2 + i1 * 64 + hp] = lo;
            if (i2 < Fq) {
                split2(c2[mt][nt][2], c2[mt][nt][3], hi, lo);
                g_Shi[(size_t)b * KP_CIN2 + i2 * 64 + hp] = hi;
                g_Slo[(size_t)b * KP_CIN2 + i2 * 64 + hp] = lo;
            } else if (i2 == Fq) {
                g_cin1[b * Hq + h]     = c2[mt][nt][2];
                g_cin1[b * Hq + h + 1] = c2[mt][nt][3];
            }
        }
    }
}

// ---------------- packed GEMM (ldmatrix + split-K via blockIdx.z) ----------------
// BM=128, BN=128, BK=16 (8 kp); A [M][pitchA] row-major, B n-major [Npad][pitchB].
#define G_SMEM 49152
__global__ __launch_bounds__(256) void gemm_pk(
    const u32* __restrict__ Agh, const u32* __restrict__ Agl, int pitchA,
    const u32* __restrict__ Bgh, const u32* __restrict__ Bgl, int pitchB, int N,
    int kpSeg, int Mtot,
    const float* __restrict__ bias, int relu,
    float* __restrict__ Cf, u32* __restrict__ Ch, u32* __restrict__ Cl)
{
    extern __shared__ char dsm_c[];
    u32* dsm = (u32*)dsm_c;
    int tid  = threadIdx.x;
    int warp = tid >> 5, lane = tid & 31;
    int gid  = lane >> 2, tg = lane & 3;
    int wm   = warp & 3, wn = warp >> 2;
    int m0 = blockIdx.y * 128, n0 = blockIdx.x * 128;
    int kpOff = blockIdx.z * kpSeg;
    if (Cf) Cf += (size_t)blockIdx.z * Mtot * N;

    int sr = tid >> 1, sq = tid & 1;
    const u32* pAh = Agh + (size_t)(m0 + sr) * pitchA + kpOff + sq * 4;
    const u32* pAl = Agl + (size_t)(m0 + sr) * pitchA + kpOff + sq * 4;
    const u32* pBh = Bgh + (size_t)(n0 + sr) * pitchB + kpOff + sq * 4;
    const u32* pBl = Bgl + (size_t)(n0 + sr) * pitchB + kpOff + sq * 4;
    int sidx = sr * 12 + sq * 4;

    int la_off = ((lane & 7) + (lane & 8)) * 12 + ((lane & 16) >> 2);
    int lb_off = ((lane & 7) + ((lane & 16) >> 1)) * 12 + ((lane & 8) >> 1);
    u32 smbase = smem_u32(dsm_c);

    float c[2][8][4];
#pragma unroll
    for (int mt = 0; mt < 2; mt++)
#pragma unroll
        for (int nt = 0; nt < 8; nt++)
#pragma unroll
            for (int r = 0; r < 4; r++) c[mt][nt][r] = 0.f;

    int T = kpSeg >> 3;
    {   // prologue: stage tile 0 into buf 0
        uint4 xah = *(const uint4*)pAh;
        uint4 xal = *(const uint4*)pAl;
        uint4 xbh = *(const uint4*)pBh;
        uint4 xbl = *(const uint4*)pBl;
        *(uint4*)&dsm[sidx]        = xah;
        *(uint4*)&dsm[3072 + sidx] = xal;
        *(uint4*)&dsm[6144 + sidx] = xbh;
        *(uint4*)&dsm[9216 + sidx] = xbl;
    }
    __syncthreads();
    int buf = 0;

#pragma unroll 1
    for (int t = 0; t < T; t++) {
        uint4 xah, xal, xbh, xbl;
        bool have = (t + 1 < T);
        if (have) {
            int o = (t + 1) * 8;
            xah = *(const uint4*)(pAh + o);
            xal = *(const uint4*)(pAl + o);
            xbh = *(const uint4*)(pBh + o);
            xbl = *(const uint4*)(pBl + o);
        }

        u32 aBase = smbase + (buf * 1536) * 4;
        u32 bBase = smbase + ((6144 + buf * 1536)) * 4;
        u32 ah[2][4], al[2][4];
#pragma unroll
        for (int mt = 0; mt < 2; mt++) {
            u32 ad = aBase + ((wm * 32 + mt * 16) * 12 + la_off) * 4;
            ldsm4(ah[mt][0], ah[mt][1], ah[mt][2], ah[mt][3], ad);
            ldsm4(al[mt][0], al[mt][1], al[mt][2], al[mt][3], ad + 3072 * 4);
        }
#pragma unroll
        for (int np = 0; np < 4; np++) {
            u32 bd = bBase + ((wn * 64 + np * 16) * 12 + lb_off) * 4;
            u32 bh[4], bl[4];
            ldsm4(bh[0], bh[1], bh[2], bh[3], bd);
            ldsm4(bl[0], bl[1], bl[2], bl[3], bd + 3072 * 4);
#pragma unroll
            for (int mt = 0; mt < 2; mt++) {
                mma16816(c[mt][2 * np],     ah[mt], bh[0], bh[1]);
                mma16816(c[mt][2 * np],     ah[mt], bl[0], bl[1]);
                mma16816(c[mt][2 * np],     al[mt], bh[0], bh[1]);
                mma16816(c[mt][2 * np + 1], ah[mt], bh[2], bh[3]);
                mma16816(c[mt][2 * np + 1], ah[mt], bl[2], bl[3]);
                mma16816(c[mt][2 * np + 1], al[mt], bh[2], bh[3]);
            }
        }

        if (have) {
            int nb = buf ^ 1;
            *(uint4*)&dsm[nb * 1536 + sidx]        = xah;
            *(uint4*)&dsm[3072 + nb * 1536 + sidx] = xal;
            *(uint4*)&dsm[6144 + nb * 1536 + sidx] = xbh;
            *(uint4*)&dsm[9216 + nb * 1536 + sidx] = xbl;
            __syncthreads();
            buf = nb;
        }
    }

    // epilogue
    int Np = N >> 1;
#pragma unroll
    for (int mt = 0; mt < 2; mt++) {
        int r0 = m0 + wm * 32 + mt * 16 + gid;
#pragma unroll
        for (int nt = 0; nt < 8; nt++) {
            int col = n0 + wn * 64 + nt * 8 + 2 * tg;
            if (col >= N) continue;
            float b0v = bias ? bias[col] : 0.f;
            float b1v = bias ? bias[col + 1] : 0.f;
            float v0 = c[mt][nt][0] + b0v, v1 = c[mt][nt][1] + b1v;
            float v2 = c[mt][nt][2] + b0v, v3 = c[mt][nt][3] + b1v;
            if (relu) {
                v0 = fmaxf(v0, 0.f); v1 = fmaxf(v1, 0.f);
                v2 = fmaxf(v2, 0.f); v3 = fmaxf(v3, 0.f);
            }
            if (Cf) {
                *(float2*)&Cf[(size_t)r0 * N + col]       = make_float2(v0, v1);
                *(float2*)&Cf[(size_t)(r0 + 8) * N + col] = make_float2(v2, v3);
            }
            if (Ch) {
                u32 hi, lo;
                split2(v0, v1, hi, lo);
                Ch[(size_t)r0 * Np + (col >> 1)] = hi;
                Cl[(size_t)r0 * Np + (col >> 1)] = lo;
                split2(v2, v3, hi, lo);
                Ch[(size_t)(r0 + 8) * Np + (col >> 1)] = hi;
                Cl[(size_t)(r0 + 8) * Np + (col >> 1)] = lo;
            }
        }
    }
}

// ---------------- final head ----------------
__global__ void final_kernel(const float* __restrict__ dense,
                             const float* __restrict__ w_out,
                             const float* __restrict__ b_out,
                             float* __restrict__ out) {
    int gt = blockIdx.x * blockDim.x + threadIdx.x;
    int b = gt >> 5, lane = gt & 31;
    if (b >= Bq) return;
    float a = 0.f;
    const float* c1 = g_cin1 + b * Hq;
    const float* c2a = g_cin2s + b * Hq;
    const float* c2b = g_cin2s + 1 * Bq * Hq + b * Hq;
    const float* c2c = g_cin2s + 2 * Bq * Hq + b * Hq;
    const float* c2d = g_cin2s + 3 * Bq * Hq + b * Hq;
    const float* hh = g_h2 + b * Uq;
    for (int t = lane; t < Hq; t += 32) a += c1[t] * w_out[1 + t];
    for (int t = lane; t < Hq; t += 32)
        a += (c2a[t] + c2b[t] + c2c[t] + c2d[t]) * w_out[1 + Hq + t];
    for (int t = lane; t < Uq; t += 32) a += hh[t] * w_out[1 + 2 * Hq + t];
    if (lane < 13) a += dense[b * 13 + lane] * w_out[1 + 2 * Hq + Uq + lane];
#pragma unroll
    for (int o = 16; o > 0; o >>= 1) a += __shfl_down_sync(0xffffffffu, a, o);
    if (lane == 0) {
        float tot = a + g_lin[b] * w_out[0] + b_out[0];
        float o;
        if (tot >= 0.f) { o = 1.f / (1.f + expf(-tot)); }
        else            { float e = expf(tot); o = e / (1.f + e); }
        out[b] = o;
    }
}

extern "C" void kernel_launch(void* const* d_in, const int* in_sizes, int n_in,
                              void* d_out, int out_size) {
    (void)in_sizes; (void)n_in; (void)out_size;
    const float* dense  = (const float*)d_in[0];
    const int*   sparse = (const int*)  d_in[1];
    const float* E      = (const float*)d_in[2];
    const float* W0     = (const float*)d_in[3];
    const float* Wc1    = (const float*)d_in[4];
    const float* W1     = (const float*)d_in[5];
    const float* b1     = (const float*)d_in[6];
    const float* W2     = (const float*)d_in[7];
    const float* b2     = (const float*)d_in[8];
    const float* w_lin  = (const float*)d_in[9];
    const float* b_lin  = (const float*)d_in[10];
    const float* w_out  = (const float*)d_in[11];
    const float* b_out  = (const float*)d_in[12];
    float* out = (float*)d_out;

    static int smem_set = 0;
    if (!smem_set) {
        cudaFuncSetAttribute(x1s_mma_kernel,
                             cudaFuncAttributeMaxDynamicSharedMemorySize, X1_SMEM);
        cudaFuncSetAttribute(gemm_pk,
                             cudaFuncAttributeMaxDynamicSharedMemorySize, G_SMEM);
        smem_set = 1;
    }

    void *pShi, *pSlo, *pEhi, *pElo, *pWc1hi, *pWc1lo, *pW1hi, *pW1lo,
         *pW2hi, *pW2lo, *pH1hi, *pH1lo, *pC2, *pH2;
    cudaGetSymbolAddress(&pShi, g_Shi);   cudaGetSymbolAddress(&pSlo, g_Slo);
    cudaGetSymbolAddress(&pEhi, g_Ehi);   cudaGetSymbolAddress(&pElo, g_Elo);
    cudaGetSymbolAddress(&pWc1hi, g_Wc1hi); cudaGetSymbolAddress(&pWc1lo, g_Wc1lo);
    cudaGetSymbolAddress(&pW1hi, g_W1hi); cudaGetSymbolAddress(&pW1lo, g_W1lo);
    cudaGetSymbolAddress(&pW2hi, g_W2hi); cudaGetSymbolAddress(&pW2lo, g_W2lo);
    cudaGetSymbolAddress(&pH1hi, g_H1hi); cudaGetSymbolAddress(&pH1lo, g_H1lo);
    cudaGetSymbolAddress(&pC2, g_cin2s);  cudaGetSymbolAddress(&pH2, g_h2);

    // launches 1-3 are x1's dependencies; x1 is launch #4 (ncu captures #4)
    prep_kernel<<<(NPAIR * Hq + 255) / 256, 256>>>(W0);
    pack_wsymT<<<(Hq * KPP_X1 + 255) / 256, 256>>>();
    gather_kernel<<<(Bq * Fq * (Dq / 4) + 255) / 256, 256>>>(sparse, E);

    x1s_mma_kernel<<<Bq / 4, 256, X1_SMEM>>>(sparse, E);

    lin_kernel<<<(Bq + 255) / 256, 256>>>(sparse, w_lin, b_lin);
    packB_T<<<(Hq * KP_CIN2 + 255) / 256, 256>>>(
        Wc1, Fq * Hq, Hq, KP_CIN2, Hq, (u32*)pWc1hi, (u32*)pWc1lo);
    packB_T<<<(512 * KP_MLP1 + 255) / 256, 256>>>(
        W1, Fq * Dq, Uq, KP_MLP1, 512, (u32*)pW1hi, (u32*)pW1lo);
    packB_T<<<(512 * KP_MLP2 + 255) / 256, 256>>>(
        W2, Uq, Uq, KP_MLP2, 512, (u32*)pW2hi, (u32*)pW2lo);

    // cin2 = S @ Wc1, split-K x4 in one launch (grid.z = 4, 256 blocks)
    gemm_pk<<<dim3(1, Bq / 128, 4), 256, G_SMEM>>>(
        (const u32*)pShi, (const u32*)pSlo, KP_CIN2,
        (const u32*)pWc1hi, (const u32*)pWc1lo, KP_CIN2, Hq,
        KP_SPLIT4, Bq, nullptr, 0, (float*)pC2, nullptr, nullptr);
    // h1 = relu(embed @ W1 + b1) -> packed split only
    gemm_pk<<<dim3((Uq + 127) / 128, Bq / 128, 1), 256, G_SMEM>>>(
        (const u32*)pEhi, (const u32*)pElo, KP_MLP1,
        (const u32*)pW1hi, (const u32*)pW1lo, KP_MLP1, Uq,
        KP_MLP1, Bq, b1, 1, nullptr, (u32*)pH1hi, (u32*)pH1lo);
    // h2 = relu(h1 @ W2 + b2) -> fp32
    gemm_pk<<<dim3((Uq + 127) / 128, Bq / 128, 1), 256, G_SMEM>>>(
        (const u32*)pH1hi, (const u32*)pH1lo, KP_MLP2,
        (const u32*)pW2hi, (const u32*)pW2lo, KP_MLP2, Uq,
        KP_MLP2, Bq, b2, 1, (float*)pH2, nullptr, nullptr);

    final_kernel<<<(Bq * 32 + 255) / 256, 256>>>(dense, w_out, b_out, out);
}